// round 6
// baseline (speedup 1.0000x reference)
#include <cuda_runtime.h>
#include <cuda_bf16.h>
#include <math.h>
#include <stdint.h>

// Problem constants
#define Lc 4096
#define Ec 256
#define Hc 128
#define Tc 64
#define Dc 12
#define Nc 8191            // 2*L-1
#define NEDGE 8190         // N-1

typedef unsigned long long ull;

// ---------------- packed f32x2 helpers ------------------------------------
__device__ __forceinline__ void fma2(ull& d, ull a, ull b) {
    asm("fma.rn.f32x2 %0, %1, %2, %0;" : "+l"(d) : "l"(a), "l"(b));
}
__device__ __forceinline__ ull splat2(float a) {
    ull r; asm("mov.b64 %0, {%1, %1};" : "=l"(r) : "f"(a)); return r;
}
__device__ __forceinline__ float2 unpk(ull v) {
    float2 r; asm("mov.b64 {%0, %1}, %2;" : "=f"(r.x), "=f"(r.y) : "l"(v)); return r;
}

// ---------------- fast activations ----------------------------------------
__device__ __forceinline__ float fast_sig(float x) {
    float t;
    asm("ex2.approx.f32 %0, %1;" : "=f"(t) : "f"(-1.4426950408889634f * x));
    float r;
    asm("rcp.approx.f32 %0, %1;" : "=f"(r) : "f"(1.0f + t));
    return r;
}
__device__ __forceinline__ float fast_tanh(float x) {
    float r; asm("tanh.approx.f32 %0, %1;" : "=f"(r) : "f"(x)); return r;
}

// ---------------- scratch (device globals; no allocation) ----------------
__device__ float g_xg[Lc * 512];                 // W_ih@x + b_ih + b_hh   (8 MB)
__device__ float g_hidden[Nc * Hc];              // node hidden states
__device__ float g_unary[Nc * Tc];
__device__ float g_v2f[Nc * Tc];
__device__ float g_f2p[Nc * Tc];
__device__ float g_f2n[Nc * Tc];
__device__ float g_edge[(size_t)NEDGE * 4096];   // edge factors (134 MB)

// ---------------- Stage A: embedding + input projection -------------------
__global__ void embed_gemm_kernel(const int* __restrict__ tokens,
                                  const float* __restrict__ emb,
                                  const float* __restrict__ W_ih,
                                  const float* __restrict__ b_ih,
                                  const float* __restrict__ b_hh) {
    __shared__ float es[4][256];
    int t0 = blockIdx.x * 4;
    int tid = threadIdx.x;
    for (int i = tid; i < 4 * 256; i += 128) {
        int tl = i >> 8, k = i & 255;
        es[tl][k] = emb[(size_t)tokens[t0 + tl] * Ec + k];
    }
    __syncthreads();
    for (int r = 0; r < 4; r++) {
        int j = tid + 128 * r;
        float a0 = 0.f, a1 = 0.f, a2 = 0.f, a3 = 0.f;
        const float4* w4 = (const float4*)(W_ih + (size_t)j * 256);
        const float4* e0 = (const float4*)es[0];
        const float4* e1 = (const float4*)es[1];
        const float4* e2 = (const float4*)es[2];
        const float4* e3 = (const float4*)es[3];
#pragma unroll 8
        for (int k = 0; k < 64; k++) {
            float4 w = __ldg(&w4[k]);
            float4 v;
            v = e0[k]; a0 += w.x * v.x + w.y * v.y + w.z * v.z + w.w * v.w;
            v = e1[k]; a1 += w.x * v.x + w.y * v.y + w.z * v.z + w.w * v.w;
            v = e2[k]; a2 += w.x * v.x + w.y * v.y + w.z * v.z + w.w * v.w;
            v = e3[k]; a3 += w.x * v.x + w.y * v.y + w.z * v.z + w.w * v.w;
        }
        float bias = b_ih[j] + b_hh[j];
        g_xg[(size_t)(t0 + 0) * 512 + j] = a0 + bias;
        g_xg[(size_t)(t0 + 1) * 512 + j] = a1 + bias;
        g_xg[(size_t)(t0 + 2) * 512 + j] = a2 + bias;
        g_xg[(size_t)(t0 + 3) * 512 + j] = a3 + bias;
    }
}

// ---------------- Stage B: sequential LSTM (single CTA, 512 thr) ----------
// Each lane owns ONE full gate row in registers (128 cols = 32 ull = 64 regs).
// Warp w owns h outputs j = 8w..8w+7. Lane l: gate = l>>3, j' = l&7,
// row R = 128*gate + 8*w + j'. Gates for output j' are gathered with 4
// intra-warp shfls; lanes 0-7 run the activation with c in a register.
// ONE __syncthreads per step.
__global__ void __launch_bounds__(512, 1) lstm_kernel(const float* __restrict__ W_hh) {
    __shared__ __align__(16) float hsm[128];

    int tid  = threadIdx.x;
    int w    = tid >> 5;
    int lane = tid & 31;
    int jloc = lane & 7;                 // 0..7
    int gate = lane >> 3;                // 0..3 (i,f,g,o)
    int row  = 128 * gate + 8 * w + jloc;
    int hidx = 8 * w + jloc;             // h output this lane may own (lanes 0-7)

    // full row of W_hh in registers: 32 ull = 64 floats
    ull wr[32];
    const ull* wsrc = (const ull*)(W_hh + (size_t)row * 128);
#pragma unroll
    for (int i = 0; i < 32; i++) wr[i] = wsrc[i];

    if (tid < 128) hsm[tid] = 0.f;
    float c_reg = 0.f;
    __syncthreads();

    float* leaf = g_hidden + (size_t)(Lc - 1) * Hc;

    // 2-deep xg prefetch
    float xg0 = g_xg[row];
    float xg1 = g_xg[512 + row];

    for (int t = 0; t < Lc; t++) {
        // prefetch t+2
        float xg2 = 0.f;
        if (t + 2 < Lc) xg2 = g_xg[(size_t)(t + 2) * 512 + row];

        ull a0 = 0ull, a1 = 0ull, a2 = 0ull, a3 = 0ull;
        const ulonglong2* h16 = (const ulonglong2*)hsm;
#pragma unroll
        for (int k = 0; k < 16; k += 2) {
            ulonglong2 hv0 = h16[k];
            ulonglong2 hv1 = h16[k + 1];
            fma2(a0, wr[2 * k],     hv0.x);
            fma2(a1, wr[2 * k + 1], hv0.y);
            fma2(a2, wr[2 * k + 2], hv1.x);
            fma2(a3, wr[2 * k + 3], hv1.y);
        }
        float2 s0 = unpk(a0), s1 = unpk(a1), s2 = unpk(a2), s3 = unpk(a3);
        float G = ((s0.x + s0.y) + (s1.x + s1.y))
                + ((s2.x + s2.y) + (s3.x + s3.y)) + xg0;

        // gather the 4 gate pre-activations for output jloc
        float gi = __shfl_sync(0xffffffffu, G, jloc);
        float gf = __shfl_sync(0xffffffffu, G, jloc + 8);
        float gg = __shfl_sync(0xffffffffu, G, jloc + 16);
        float go = __shfl_sync(0xffffffffu, G, jloc + 24);

        if (lane < 8) {
            float c = fast_sig(gf) * c_reg + fast_sig(gi) * fast_tanh(gg);
            c_reg = c;
            float h = fast_sig(go) * fast_tanh(c);
            hsm[hidx] = h;
            leaf[(size_t)t * Hc + hidx] = h;
        }
        __syncthreads();
        xg0 = xg1;
        xg1 = xg2;
    }
}

// ---------------- Stage C: bottom-up pair fusion (8 nodes/block) ----------
__global__ void p2h_kernel(const float* __restrict__ Wp, const float* __restrict__ bp,
                           int base, int count) {
    int n0 = base + blockIdx.x * 8;
    __shared__ float pair[8][256];
    int tid = threadIdx.x;  // 128
#pragma unroll
    for (int b = 0; b < 8; b++) {
        int node = n0 + b;
        if (node < base + count) {
            pair[b][tid]       = g_hidden[(size_t)(2 * node + 1) * Hc + tid];
            pair[b][tid + 128] = g_hidden[(size_t)(2 * node + 2) * Hc + tid];
        } else {
            pair[b][tid] = 0.f; pair[b][tid + 128] = 0.f;
        }
    }
    __syncthreads();
    float a[8] = {};
    const float4* wv4 = (const float4*)(Wp + (size_t)tid * 256);
#pragma unroll 4
    for (int k = 0; k < 64; k++) {
        float4 wv = __ldg(&wv4[k]);
#pragma unroll
        for (int b = 0; b < 8; b++) {
            float4 v = ((const float4*)pair[b])[k];
            a[b] += wv.x * v.x + wv.y * v.y + wv.z * v.z + wv.w * v.w;
        }
    }
    float bias = bp[tid];
#pragma unroll
    for (int b = 0; b < 8; b++) {
        int node = n0 + b;
        if (node < base + count)
            g_hidden[(size_t)node * Hc + tid] = a[b] + bias;
    }
}

// ---------------- Stage D: unary factors (+ v2f init, f2n root zero) ------
__global__ void unary_kernel(const float* __restrict__ W_uni, const float* __restrict__ b_uni) {
    int node = blockIdx.x;
    int t = threadIdx.x;  // 64
    __shared__ float hs[128];
    hs[t] = g_hidden[(size_t)node * Hc + t];
    hs[t + 64] = g_hidden[(size_t)node * Hc + 64 + t];
    __syncthreads();
    float acc = b_uni[t];
    const float4* w = (const float4*)(W_uni + (size_t)t * 128);
    const float4* h4 = (const float4*)hs;
#pragma unroll
    for (int k = 0; k < 32; k++) {
        float4 wv = __ldg(&w[k]);
        float4 hv = h4[k];
        acc += wv.x * hv.x + wv.y * hv.y + wv.z * hv.z + wv.w * hv.w;
    }
    g_unary[(size_t)node * Tc + t] = acc;
    g_v2f[(size_t)node * Tc + t] = acc;
    if (node == 0) g_f2n[t] = 0.f;
}

// ---------------- Stage E: edge factor GEMM (f32x2) -----------------------
__global__ void __launch_bounds__(256) edge_gemm_kernel(const float* __restrict__ W,
                                                        const float* __restrict__ bias) {
    const int M = NEDGE;
    __shared__ float As[16][132];
    __shared__ float Bs[16][132];
    int m0 = blockIdx.y * 128;
    int n0 = blockIdx.x * 128;
    int tid = threadIdx.x;
    int tx = tid & 15, ty = tid >> 4;
    ull accp[8][4];
#pragma unroll
    for (int i = 0; i < 8; i++)
#pragma unroll
        for (int j = 0; j < 4; j++) accp[i][j] = 0ull;

    for (int k0 = 0; k0 < 256; k0 += 16) {
#pragma unroll
        for (int i = 0; i < 2; i++) {
            int idx = tid + i * 256;
            int m = idx & 127, k4 = idx >> 7;
            int e = m0 + m;
            float4 v = make_float4(0.f, 0.f, 0.f, 0.f);
            if (e < M) {
                int kk = k0 + k4 * 4;
                int child = e + 1, parent = e >> 1;
                const float* src = (kk < 128)
                    ? g_hidden + (size_t)parent * Hc + kk
                    : g_hidden + (size_t)child * Hc + (kk - 128);
                v = *(const float4*)src;
            }
            As[k4 * 4 + 0][m] = v.x; As[k4 * 4 + 1][m] = v.y;
            As[k4 * 4 + 2][m] = v.z; As[k4 * 4 + 3][m] = v.w;
        }
#pragma unroll
        for (int i = 0; i < 2; i++) {
            int idx = tid + i * 256;
            int n = idx & 127, k4 = idx >> 7;
            float4 v = __ldg((const float4*)(W + (size_t)(n0 + n) * 256 + k0 + k4 * 4));
            Bs[k4 * 4 + 0][n] = v.x; Bs[k4 * 4 + 1][n] = v.y;
            Bs[k4 * 4 + 2][n] = v.z; Bs[k4 * 4 + 3][n] = v.w;
        }
        __syncthreads();
#pragma unroll
        for (int kk = 0; kk < 16; kk++) {
            float4 aA = *(const float4*)&As[kk][ty * 4];
            float4 aB = *(const float4*)&As[kk][64 + ty * 4];
            ulonglong2 b0 = *(const ulonglong2*)&Bs[kk][tx * 4];
            ulonglong2 b1 = *(const ulonglong2*)&Bs[kk][64 + tx * 4];
            ull b[4] = {b0.x, b0.y, b1.x, b1.y};
            float a[8] = {aA.x, aA.y, aA.z, aA.w, aB.x, aB.y, aB.z, aB.w};
#pragma unroll
            for (int i = 0; i < 8; i++) {
                ull as = splat2(a[i]);
#pragma unroll
                for (int j = 0; j < 4; j++) fma2(accp[i][j], as, b[j]);
            }
        }
        __syncthreads();
    }
#pragma unroll
    for (int hi = 0; hi < 2; hi++) {
#pragma unroll
        for (int i = 0; i < 4; i++) {
            int m = m0 + hi * 64 + ty * 4 + i;
            if (m < M) {
#pragma unroll
                for (int hj = 0; hj < 2; hj++) {
                    int n = n0 + hj * 64 + tx * 4;
                    float2 v0 = unpk(accp[hi * 4 + i][hj * 2 + 0]);
                    float2 v1 = unpk(accp[hi * 4 + i][hj * 2 + 1]);
                    float4 o = make_float4(v0.x + bias[n], v0.y + bias[n + 1],
                                           v1.x + bias[n + 2], v1.y + bias[n + 3]);
                    *(float4*)(g_edge + (size_t)m * 4096 + n) = o;
                }
            }
        }
    }
}

// ---------------- Stage F: upward pass (one level) ------------------------
__global__ void up_kernel(int base, int leafLevel, int hasParent) {
    int idx = base + blockIdx.x;
    int t = threadIdx.x;  // 64
    __shared__ float v[64];
    float val = g_v2f[(size_t)idx * Tc + t];
    if (!leafLevel) {
        val += g_f2p[(size_t)(2 * idx + 1) * Tc + t] + g_f2p[(size_t)(2 * idx + 2) * Tc + t];
        g_v2f[(size_t)idx * Tc + t] = val;
    }
    v[t] = val;
    __syncthreads();
    if (hasParent) {
        const float4* row = (const float4*)(g_edge + (size_t)(idx - 1) * 4096 + t * 64);
        float r[64];
#pragma unroll
        for (int c = 0; c < 16; c++) {
            float4 x = __ldg(row + c);
            r[4 * c] = x.x; r[4 * c + 1] = x.y; r[4 * c + 2] = x.z; r[4 * c + 3] = x.w;
        }
        float m = -3.4e38f;
#pragma unroll
        for (int c = 0; c < 64; c++) { r[c] += v[c]; m = fmaxf(m, r[c]); }
        float s = 0.f;
#pragma unroll
        for (int c = 0; c < 64; c++) s += __expf(r[c] - m);
        g_f2p[(size_t)idx * Tc + t] = m + __logf(s);
    }
}

// ---------------- Stage G: downward pass (one level) ----------------------
__global__ void down_kernel(int base) {
    int idx = base + blockIdx.x;
    int t = threadIdx.x;  // 64
    int par = (idx - 1) >> 1;
    int sib = (idx & 1) ? idx + 1 : idx - 1;
    __shared__ float p[64];
    p[t] = g_unary[(size_t)par * Tc + t] + g_f2n[(size_t)par * Tc + t]
         + g_f2p[(size_t)sib * Tc + t];
    __syncthreads();
    const float* e0 = g_edge + (size_t)(idx - 1) * 4096 + t;
    float r[64];
    float m = -3.4e38f;
#pragma unroll
    for (int tp = 0; tp < 64; tp++) {
        r[tp] = e0[(size_t)tp * 64] + p[tp];
        m = fmaxf(m, r[tp]);
    }
    float s = 0.f;
#pragma unroll
    for (int tp = 0; tp < 64; tp++) s += __expf(r[tp] - m);
    g_f2n[(size_t)idx * Tc + t] = m + __logf(s);
}

// ---------------- Stage H: beliefs + postorder scatter --------------------
__global__ void out_kernel(float* __restrict__ out) {
    int node = blockIdx.x;
    int t = threadIdx.x;  // 64
    int x = node + 1;
    int d = 31 - __clz(x);
    int start = 0, size = Nc;
    for (int b = d - 1; b >= 0; b--) {
        int half = (size - 1) >> 1;
        if ((x >> b) & 1) start += half;
        size = half;
    }
    int post = start + size - 1;
    out[(size_t)post * Tc + t] = g_v2f[(size_t)node * Tc + t] + g_f2n[(size_t)node * Tc + t];
}

// ---------------- launch ---------------------------------------------------
extern "C" void kernel_launch(void* const* d_in, const int* in_sizes, int n_in,
                              void* d_out, int out_size) {
    const int*   tokens = (const int*)d_in[0];
    const float* emb    = (const float*)d_in[1];
    const float* W_ih   = (const float*)d_in[2];
    const float* W_hh   = (const float*)d_in[3];
    const float* b_ih   = (const float*)d_in[4];
    const float* b_hh   = (const float*)d_in[5];
    const float* W_p2h  = (const float*)d_in[6];
    const float* b_p2h  = (const float*)d_in[7];
    const float* W_uni  = (const float*)d_in[8];
    const float* b_uni  = (const float*)d_in[9];
    const float* W_edge = (const float*)d_in[10];
    const float* b_edge = (const float*)d_in[11];
    float* out = (float*)d_out;

    // A: embedding + input projection
    embed_gemm_kernel<<<Lc / 4, 128>>>(tokens, emb, W_ih, b_ih, b_hh);
    // B: sequential LSTM (all weights in registers, one barrier/step)
    lstm_kernel<<<1, 512>>>(W_hh);
    // C: bottom-up fusion, levels D-1 .. 0
    for (int d = Dc - 1; d >= 0; d--) {
        int base = (1 << d) - 1;
        int count = 1 << d;
        p2h_kernel<<<(count + 7) / 8, 128>>>(W_p2h, b_p2h, base, count);
    }
    // D: unary factors
    unary_kernel<<<Nc, 64>>>(W_uni, b_uni);
    // E: edge factor GEMM
    {
        dim3 grid(4096 / 128, (NEDGE + 127) / 128);
        edge_gemm_kernel<<<grid, 256>>>(W_edge, b_edge);
    }
    // F: upward pass, levels D .. 0
    for (int d = Dc; d >= 0; d--) {
        int base = (1 << d) - 1;
        up_kernel<<<(1 << d), 64>>>(base, d == Dc ? 1 : 0, d > 0 ? 1 : 0);
    }
    // G: downward pass, levels 1 .. D
    for (int d = 1; d <= Dc; d++) {
        int base = (1 << d) - 1;
        down_kernel<<<(1 << d), 64>>>(base);
    }
    // H: beliefs in postorder
    out_kernel<<<Nc, 64>>>(out);
}

// round 7
// speedup vs baseline: 1.2882x; 1.2882x over previous
#include <cuda_runtime.h>
#include <cuda_bf16.h>
#include <math.h>
#include <stdint.h>

// Problem constants
#define Lc 4096
#define Ec 256
#define Hc 128
#define Tc 64
#define Dc 12
#define Nc 8191            // 2*L-1
#define NEDGE 8190         // N-1

typedef unsigned long long ull;

// ---------------- packed f32x2 helpers ------------------------------------
__device__ __forceinline__ void fma2(ull& d, ull a, ull b) {
    asm("fma.rn.f32x2 %0, %1, %2, %0;" : "+l"(d) : "l"(a), "l"(b));
}
__device__ __forceinline__ ull splat2(float a) {
    ull r; asm("mov.b64 %0, {%1, %1};" : "=l"(r) : "f"(a)); return r;
}
__device__ __forceinline__ float2 unpk(ull v) {
    float2 r; asm("mov.b64 {%0, %1}, %2;" : "=f"(r.x), "=f"(r.y) : "l"(v)); return r;
}

// ---------------- fast activations ----------------------------------------
__device__ __forceinline__ float fast_tanh(float x) {
    float r; asm("tanh.approx.f32 %0, %1;" : "=f"(r) : "f"(x)); return r;
}
__device__ __forceinline__ float fast_sig(float x) {
    // sigmoid(x) = 0.5 + 0.5*tanh(0.5x)  -- single MUFU
    return fmaf(0.5f, fast_tanh(0.5f * x), 0.5f);
}

// ---------------- scratch (device globals; no allocation) ----------------
__device__ float g_xg[Lc * 512];                 // W_ih@x + b_ih + b_hh   (8 MB)
__device__ float g_hidden[Nc * Hc];              // node hidden states
__device__ float g_unary[Nc * Tc];
__device__ float g_v2f[Nc * Tc];
__device__ float g_f2p[Nc * Tc];
__device__ float g_f2n[Nc * Tc];
__device__ float g_edge[(size_t)NEDGE * 4096];   // edge factors (134 MB)

// ---------------- Stage A: embedding + input projection -------------------
__global__ void embed_gemm_kernel(const int* __restrict__ tokens,
                                  const float* __restrict__ emb,
                                  const float* __restrict__ W_ih,
                                  const float* __restrict__ b_ih,
                                  const float* __restrict__ b_hh) {
    __shared__ float es[4][256];
    int t0 = blockIdx.x * 4;
    int tid = threadIdx.x;
    for (int i = tid; i < 4 * 256; i += 128) {
        int tl = i >> 8, k = i & 255;
        es[tl][k] = emb[(size_t)tokens[t0 + tl] * Ec + k];
    }
    __syncthreads();
    for (int r = 0; r < 4; r++) {
        int j = tid + 128 * r;
        float a0 = 0.f, a1 = 0.f, a2 = 0.f, a3 = 0.f;
        const float4* w4 = (const float4*)(W_ih + (size_t)j * 256);
        const float4* e0 = (const float4*)es[0];
        const float4* e1 = (const float4*)es[1];
        const float4* e2 = (const float4*)es[2];
        const float4* e3 = (const float4*)es[3];
#pragma unroll 8
        for (int k = 0; k < 64; k++) {
            float4 w = __ldg(&w4[k]);
            float4 v;
            v = e0[k]; a0 += w.x * v.x + w.y * v.y + w.z * v.z + w.w * v.w;
            v = e1[k]; a1 += w.x * v.x + w.y * v.y + w.z * v.z + w.w * v.w;
            v = e2[k]; a2 += w.x * v.x + w.y * v.y + w.z * v.z + w.w * v.w;
            v = e3[k]; a3 += w.x * v.x + w.y * v.y + w.z * v.z + w.w * v.w;
        }
        float bias = b_ih[j] + b_hh[j];
        g_xg[(size_t)(t0 + 0) * 512 + j] = a0 + bias;
        g_xg[(size_t)(t0 + 1) * 512 + j] = a1 + bias;
        g_xg[(size_t)(t0 + 2) * 512 + j] = a2 + bias;
        g_xg[(size_t)(t0 + 3) * 512 + j] = a3 + bias;
    }
}

// ---------------- Stage B: sequential LSTM (single CTA, 1024 thr) ---------
// R4 skeleton: each thread owns half a gate row (64 cols = 16 ull) in regs.
// Lanes 0-15: rows w*16+l cols 0-63 (h from hA); lanes 16-31: same rows,
// cols 64-127 (h from bank-skewed copy hB). shfl.xor(16) pair-reduce.
// Barrier split: warps 4-31 arrive(1)+sync(2); warps 0-3 sync(1), dense
// activation (c in registers, tanh-based sigmoid), arrive(2).
// smem float layout:
//   [0,512)    g_s
//   [512,640)  hA
//   [772,900)  hB (skewed: base bank offset 4)
__global__ void __launch_bounds__(1024, 1) lstm_kernel(const float* __restrict__ W_hh) {
    __shared__ __align__(16) float sm[904];
    float* g_s = sm;
    float* hA  = sm + 512;
    float* hB  = sm + 772;

    int tid  = threadIdx.x;
    int w    = tid >> 5;
    int lane = tid & 31;
    int half = lane >> 4;               // 0: cols 0-63, 1: cols 64-127
    int row  = w * 16 + (lane & 15);    // gate row 0..511

    // weights: 16 ull = 64 floats (half a row)
    ull wr[16];
    const ull* wsrc = (const ull*)(W_hh + (size_t)row * 128 + half * 64);
#pragma unroll
    for (int i = 0; i < 16; i++) wr[i] = wsrc[i];

    if (tid < 128) { hA[tid] = 0.f; hB[tid] = 0.f; }
    float c_reg = 0.f;
    __syncthreads();

    const ulonglong2* hp = half ? (const ulonglong2*)(hB + 64)
                                : (const ulonglong2*)hA;

    float* leaf = g_hidden + (size_t)(Lc - 1) * Hc;
    float xg = g_xg[row];

    for (int t = 0; t < Lc; t++) {
        float xg_n = 0.f;
        if (t + 1 < Lc) xg_n = g_xg[(size_t)(t + 1) * 512 + row];

        ull acc0 = 0ull, acc1 = 0ull;
#pragma unroll
        for (int k = 0; k < 8; k++) {
            ulonglong2 hv = hp[k];
            fma2(acc0, wr[2 * k],     hv.x);
            fma2(acc1, wr[2 * k + 1], hv.y);
        }
        float2 s0 = unpk(acc0), s1 = unpk(acc1);
        float partial = (s0.x + s0.y) + (s1.x + s1.y);
        float other = __shfl_xor_sync(0xffffffffu, partial, 16);
        if (half == 0) g_s[row] = partial + other + xg;

        if (tid < 128) {
            asm volatile("bar.sync 1, 1024;" ::: "memory");
            float gi = g_s[tid];
            float gf = g_s[tid + 128];
            float gg = g_s[tid + 256];
            float go = g_s[tid + 384];
            float c = fast_sig(gf) * c_reg + fast_sig(gi) * fast_tanh(gg);
            c_reg = c;
            float h = fast_sig(go) * fast_tanh(c);
            hA[tid] = h;
            hB[tid] = h;
            leaf[(size_t)t * Hc + tid] = h;
            asm volatile("bar.arrive 2, 1024;" ::: "memory");
        } else {
            asm volatile("bar.arrive 1, 1024;" ::: "memory");
            asm volatile("bar.sync 2, 1024;" ::: "memory");
        }
        xg = xg_n;
    }
}

// ---------------- Stage C: bottom-up pair fusion (8 nodes/block) ----------
__global__ void p2h_kernel(const float* __restrict__ Wp, const float* __restrict__ bp,
                           int base, int count) {
    int n0 = base + blockIdx.x * 8;
    __shared__ float pair[8][256];
    int tid = threadIdx.x;  // 128
#pragma unroll
    for (int b = 0; b < 8; b++) {
        int node = n0 + b;
        if (node < base + count) {
            pair[b][tid]       = g_hidden[(size_t)(2 * node + 1) * Hc + tid];
            pair[b][tid + 128] = g_hidden[(size_t)(2 * node + 2) * Hc + tid];
        } else {
            pair[b][tid] = 0.f; pair[b][tid + 128] = 0.f;
        }
    }
    __syncthreads();
    float a[8] = {};
    const float4* wv4 = (const float4*)(Wp + (size_t)tid * 256);
#pragma unroll 4
    for (int k = 0; k < 64; k++) {
        float4 wv = __ldg(&wv4[k]);
#pragma unroll
        for (int b = 0; b < 8; b++) {
            float4 v = ((const float4*)pair[b])[k];
            a[b] += wv.x * v.x + wv.y * v.y + wv.z * v.z + wv.w * v.w;
        }
    }
    float bias = bp[tid];
#pragma unroll
    for (int b = 0; b < 8; b++) {
        int node = n0 + b;
        if (node < base + count)
            g_hidden[(size_t)node * Hc + tid] = a[b] + bias;
    }
}

// ---------------- Stage D: unary factors (+ v2f init, f2n root zero) ------
__global__ void unary_kernel(const float* __restrict__ W_uni, const float* __restrict__ b_uni) {
    int node = blockIdx.x;
    int t = threadIdx.x;  // 64
    __shared__ float hs[128];
    hs[t] = g_hidden[(size_t)node * Hc + t];
    hs[t + 64] = g_hidden[(size_t)node * Hc + 64 + t];
    __syncthreads();
    float acc = b_uni[t];
    const float4* w = (const float4*)(W_uni + (size_t)t * 128);
    const float4* h4 = (const float4*)hs;
#pragma unroll
    for (int k = 0; k < 32; k++) {
        float4 wv = __ldg(&w[k]);
        float4 hv = h4[k];
        acc += wv.x * hv.x + wv.y * hv.y + wv.z * hv.z + wv.w * hv.w;
    }
    g_unary[(size_t)node * Tc + t] = acc;
    g_v2f[(size_t)node * Tc + t] = acc;
    if (node == 0) g_f2n[t] = 0.f;
}

// ---------------- Stage E: edge factor GEMM (f32x2) -----------------------
__global__ void __launch_bounds__(256) edge_gemm_kernel(const float* __restrict__ W,
                                                        const float* __restrict__ bias) {
    const int M = NEDGE;
    __shared__ float As[16][132];
    __shared__ float Bs[16][132];
    int m0 = blockIdx.y * 128;
    int n0 = blockIdx.x * 128;
    int tid = threadIdx.x;
    int tx = tid & 15, ty = tid >> 4;
    ull accp[8][4];
#pragma unroll
    for (int i = 0; i < 8; i++)
#pragma unroll
        for (int j = 0; j < 4; j++) accp[i][j] = 0ull;

    for (int k0 = 0; k0 < 256; k0 += 16) {
#pragma unroll
        for (int i = 0; i < 2; i++) {
            int idx = tid + i * 256;
            int m = idx & 127, k4 = idx >> 7;
            int e = m0 + m;
            float4 v = make_float4(0.f, 0.f, 0.f, 0.f);
            if (e < M) {
                int kk = k0 + k4 * 4;
                int child = e + 1, parent = e >> 1;
                const float* src = (kk < 128)
                    ? g_hidden + (size_t)parent * Hc + kk
                    : g_hidden + (size_t)child * Hc + (kk - 128);
                v = *(const float4*)src;
            }
            As[k4 * 4 + 0][m] = v.x; As[k4 * 4 + 1][m] = v.y;
            As[k4 * 4 + 2][m] = v.z; As[k4 * 4 + 3][m] = v.w;
        }
#pragma unroll
        for (int i = 0; i < 2; i++) {
            int idx = tid + i * 256;
            int n = idx & 127, k4 = idx >> 7;
            float4 v = __ldg((const float4*)(W + (size_t)(n0 + n) * 256 + k0 + k4 * 4));
            Bs[k4 * 4 + 0][n] = v.x; Bs[k4 * 4 + 1][n] = v.y;
            Bs[k4 * 4 + 2][n] = v.z; Bs[k4 * 4 + 3][n] = v.w;
        }
        __syncthreads();
#pragma unroll
        for (int kk = 0; kk < 16; kk++) {
            float4 aA = *(const float4*)&As[kk][ty * 4];
            float4 aB = *(const float4*)&As[kk][64 + ty * 4];
            ulonglong2 b0 = *(const ulonglong2*)&Bs[kk][tx * 4];
            ulonglong2 b1 = *(const ulonglong2*)&Bs[kk][64 + tx * 4];
            ull b[4] = {b0.x, b0.y, b1.x, b1.y};
            float a[8] = {aA.x, aA.y, aA.z, aA.w, aB.x, aB.y, aB.z, aB.w};
#pragma unroll
            for (int i = 0; i < 8; i++) {
                ull as = splat2(a[i]);
#pragma unroll
                for (int j = 0; j < 4; j++) fma2(accp[i][j], as, b[j]);
            }
        }
        __syncthreads();
    }
#pragma unroll
    for (int hi = 0; hi < 2; hi++) {
#pragma unroll
        for (int i = 0; i < 4; i++) {
            int m = m0 + hi * 64 + ty * 4 + i;
            if (m < M) {
#pragma unroll
                for (int hj = 0; hj < 2; hj++) {
                    int n = n0 + hj * 64 + tx * 4;
                    float2 v0 = unpk(accp[hi * 4 + i][hj * 2 + 0]);
                    float2 v1 = unpk(accp[hi * 4 + i][hj * 2 + 1]);
                    float4 o = make_float4(v0.x + bias[n], v0.y + bias[n + 1],
                                           v1.x + bias[n + 2], v1.y + bias[n + 3]);
                    *(float4*)(g_edge + (size_t)m * 4096 + n) = o;
                }
            }
        }
    }
}

// ---------------- Stage F: upward pass (one level) ------------------------
__global__ void up_kernel(int base, int leafLevel, int hasParent) {
    int idx = base + blockIdx.x;
    int t = threadIdx.x;  // 64
    __shared__ float v[64];
    float val = g_v2f[(size_t)idx * Tc + t];
    if (!leafLevel) {
        val += g_f2p[(size_t)(2 * idx + 1) * Tc + t] + g_f2p[(size_t)(2 * idx + 2) * Tc + t];
        g_v2f[(size_t)idx * Tc + t] = val;
    }
    v[t] = val;
    __syncthreads();
    if (hasParent) {
        const float4* row = (const float4*)(g_edge + (size_t)(idx - 1) * 4096 + t * 64);
        float r[64];
#pragma unroll
        for (int c = 0; c < 16; c++) {
            float4 x = __ldg(row + c);
            r[4 * c] = x.x; r[4 * c + 1] = x.y; r[4 * c + 2] = x.z; r[4 * c + 3] = x.w;
        }
        float m = -3.4e38f;
#pragma unroll
        for (int c = 0; c < 64; c++) { r[c] += v[c]; m = fmaxf(m, r[c]); }
        float s = 0.f;
#pragma unroll
        for (int c = 0; c < 64; c++) s += __expf(r[c] - m);
        g_f2p[(size_t)idx * Tc + t] = m + __logf(s);
    }
}

// ---------------- Stage G: downward pass (one level) ----------------------
__global__ void down_kernel(int base) {
    int idx = base + blockIdx.x;
    int t = threadIdx.x;  // 64
    int par = (idx - 1) >> 1;
    int sib = (idx & 1) ? idx + 1 : idx - 1;
    __shared__ float p[64];
    p[t] = g_unary[(size_t)par * Tc + t] + g_f2n[(size_t)par * Tc + t]
         + g_f2p[(size_t)sib * Tc + t];
    __syncthreads();
    const float* e0 = g_edge + (size_t)(idx - 1) * 4096 + t;
    float r[64];
    float m = -3.4e38f;
#pragma unroll
    for (int tp = 0; tp < 64; tp++) {
        r[tp] = e0[(size_t)tp * 64] + p[tp];
        m = fmaxf(m, r[tp]);
    }
    float s = 0.f;
#pragma unroll
    for (int tp = 0; tp < 64; tp++) s += __expf(r[tp] - m);
    g_f2n[(size_t)idx * Tc + t] = m + __logf(s);
}

// ---------------- Stage H: beliefs + postorder scatter --------------------
__global__ void out_kernel(float* __restrict__ out) {
    int node = blockIdx.x;
    int t = threadIdx.x;  // 64
    int x = node + 1;
    int d = 31 - __clz(x);
    int start = 0, size = Nc;
    for (int b = d - 1; b >= 0; b--) {
        int half = (size - 1) >> 1;
        if ((x >> b) & 1) start += half;
        size = half;
    }
    int post = start + size - 1;
    out[(size_t)post * Tc + t] = g_v2f[(size_t)node * Tc + t] + g_f2n[(size_t)node * Tc + t];
}

// ---------------- launch ---------------------------------------------------
extern "C" void kernel_launch(void* const* d_in, const int* in_sizes, int n_in,
                              void* d_out, int out_size) {
    const int*   tokens = (const int*)d_in[0];
    const float* emb    = (const float*)d_in[1];
    const float* W_ih   = (const float*)d_in[2];
    const float* W_hh   = (const float*)d_in[3];
    const float* b_ih   = (const float*)d_in[4];
    const float* b_hh   = (const float*)d_in[5];
    const float* W_p2h  = (const float*)d_in[6];
    const float* b_p2h  = (const float*)d_in[7];
    const float* W_uni  = (const float*)d_in[8];
    const float* b_uni  = (const float*)d_in[9];
    const float* W_edge = (const float*)d_in[10];
    const float* b_edge = (const float*)d_in[11];
    float* out = (float*)d_out;

    // A: embedding + input projection
    embed_gemm_kernel<<<Lc / 4, 128>>>(tokens, emb, W_ih, b_ih, b_hh);
    // B: sequential LSTM
    lstm_kernel<<<1, 1024>>>(W_hh);
    // C: bottom-up fusion, levels D-1 .. 0
    for (int d = Dc - 1; d >= 0; d--) {
        int base = (1 << d) - 1;
        int count = 1 << d;
        p2h_kernel<<<(count + 7) / 8, 128>>>(W_p2h, b_p2h, base, count);
    }
    // D: unary factors
    unary_kernel<<<Nc, 64>>>(W_uni, b_uni);
    // E: edge factor GEMM
    {
        dim3 grid(4096 / 128, (NEDGE + 127) / 128);
        edge_gemm_kernel<<<grid, 256>>>(W_edge, b_edge);
    }
    // F: upward pass, levels D .. 0
    for (int d = Dc; d >= 0; d--) {
        int base = (1 << d) - 1;
        up_kernel<<<(1 << d), 64>>>(base, d == Dc ? 1 : 0, d > 0 ? 1 : 0);
    }
    // G: downward pass, levels 1 .. D
    for (int d = 1; d <= Dc; d++) {
        int base = (1 << d) - 1;
        down_kernel<<<(1 << d), 64>>>(base);
    }
    // H: beliefs in postorder
    out_kernel<<<Nc, 64>>>(out);
}

// round 8
// speedup vs baseline: 1.8251x; 1.4168x over previous
#include <cuda_runtime.h>
#include <cuda_bf16.h>
#include <math.h>
#include <stdint.h>
#include <stdio.h>

// Problem constants
#define Lc 4096
#define Ec 256
#define Hc 128
#define Tc 64
#define Dc 12
#define Nc 8191            // 2*L-1
#define NEDGE 8190         // N-1

typedef unsigned long long ull;

// ---------------- packed f32x2 helpers ------------------------------------
__device__ __forceinline__ void fma2(ull& d, ull a, ull b) {
    asm("fma.rn.f32x2 %0, %1, %2, %0;" : "+l"(d) : "l"(a), "l"(b));
}
__device__ __forceinline__ ull add2(ull a, ull b) {
    ull r; asm("add.rn.f32x2 %0, %1, %2;" : "=l"(r) : "l"(a), "l"(b)); return r;
}
__device__ __forceinline__ ull splat2(float a) {
    ull r; asm("mov.b64 %0, {%1, %1};" : "=l"(r) : "f"(a)); return r;
}
__device__ __forceinline__ float2 unpk(ull v) {
    float2 r; asm("mov.b64 {%0, %1}, %2;" : "=f"(r.x), "=f"(r.y) : "l"(v)); return r;
}

// ---------------- fast activations ----------------------------------------
__device__ __forceinline__ float fast_tanh(float x) {
    float r; asm("tanh.approx.f32 %0, %1;" : "=f"(r) : "f"(x)); return r;
}
__device__ __forceinline__ float fast_sig(float x) {
    return fmaf(0.5f, fast_tanh(0.5f * x), 0.5f);
}

// ---------------- scratch (device globals; no allocation) ----------------
__device__ float g_xg[Lc * 512];                 // W_ih@x + b_ih + b_hh   (8 MB)
__device__ float g_hidden[Nc * Hc];              // node hidden states
__device__ float g_unary[Nc * Tc];
__device__ float g_v2f[Nc * Tc];
__device__ float g_f2p[Nc * Tc];
__device__ float g_f2n[Nc * Tc];
__device__ float g_edge[(size_t)NEDGE * 4096];   // edge factors (134 MB)

// ---------------- Stage A: embedding + input projection -------------------
__global__ void embed_gemm_kernel(const int* __restrict__ tokens,
                                  const float* __restrict__ emb,
                                  const float* __restrict__ W_ih,
                                  const float* __restrict__ b_ih,
                                  const float* __restrict__ b_hh) {
    __shared__ float es[4][256];
    int t0 = blockIdx.x * 4;
    int tid = threadIdx.x;
    for (int i = tid; i < 4 * 256; i += 128) {
        int tl = i >> 8, k = i & 255;
        es[tl][k] = emb[(size_t)tokens[t0 + tl] * Ec + k];
    }
    __syncthreads();
    for (int r = 0; r < 4; r++) {
        int j = tid + 128 * r;
        float a0 = 0.f, a1 = 0.f, a2 = 0.f, a3 = 0.f;
        const float4* w4 = (const float4*)(W_ih + (size_t)j * 256);
        const float4* e0 = (const float4*)es[0];
        const float4* e1 = (const float4*)es[1];
        const float4* e2 = (const float4*)es[2];
        const float4* e3 = (const float4*)es[3];
#pragma unroll 8
        for (int k = 0; k < 64; k++) {
            float4 w = __ldg(&w4[k]);
            float4 v;
            v = e0[k]; a0 += w.x * v.x + w.y * v.y + w.z * v.z + w.w * v.w;
            v = e1[k]; a1 += w.x * v.x + w.y * v.y + w.z * v.z + w.w * v.w;
            v = e2[k]; a2 += w.x * v.x + w.y * v.y + w.z * v.z + w.w * v.w;
            v = e3[k]; a3 += w.x * v.x + w.y * v.y + w.z * v.z + w.w * v.w;
        }
        float bias = b_ih[j] + b_hh[j];
        g_xg[(size_t)(t0 + 0) * 512 + j] = a0 + bias;
        g_xg[(size_t)(t0 + 1) * 512 + j] = a1 + bias;
        g_xg[(size_t)(t0 + 2) * 512 + j] = a2 + bias;
        g_xg[(size_t)(t0 + 3) * 512 + j] = a3 + bias;
    }
}

// ---------------- Stage B: sequential LSTM (single CTA, 512 thr) ----------
// Each thread owns ONE full gate row (128 cols = 32 ull = 64 regs).
// h loads are pure single-address broadcasts (all 32 lanes identical).
// Handoff via g_s[512]; warps 0-3 run the activation DENSE.
// Named-barrier split; leaf STG moved after bar.arrive (off critical path).
// smem: [0,512) g_s, [512,640) hA
__global__ void __launch_bounds__(512, 1) lstm_kernel(const float* __restrict__ W_hh) {
    __shared__ __align__(16) float sm[640];
    float* g_s = sm;
    float* hA  = sm + 512;

    int tid  = threadIdx.x;
    int row  = tid;                       // gate row 0..511

    // full row of W_hh in registers: 32 ull = 64 floats
    ull wr[32];
    const ull* wsrc = (const ull*)(W_hh + (size_t)row * 128);
#pragma unroll
    for (int i = 0; i < 32; i++) wr[i] = wsrc[i];

    if (tid < 128) hA[tid] = 0.f;
    float c_reg = 0.f;
    __syncthreads();

    float* leaf = g_hidden + (size_t)(Lc - 1) * Hc;
    float xg = g_xg[row];

    long long t_start;
    if (tid == 0) t_start = clock64();

    for (int t = 0; t < Lc; t++) {
        float xg_n = 0.f;
        if (t + 1 < Lc) xg_n = g_xg[(size_t)(t + 1) * 512 + row];

        ull a0 = 0ull, a1 = 0ull, a2 = 0ull, a3 = 0ull;
        const ulonglong2* h16 = (const ulonglong2*)hA;
#pragma unroll
        for (int k = 0; k < 16; k += 2) {
            ulonglong2 hv0 = h16[k];
            ulonglong2 hv1 = h16[k + 1];
            fma2(a0, wr[2 * k],     hv0.x);
            fma2(a1, wr[2 * k + 1], hv0.y);
            fma2(a2, wr[2 * k + 2], hv1.x);
            fma2(a3, wr[2 * k + 3], hv1.y);
        }
        ull s01 = add2(a0, a1);
        ull s23 = add2(a2, a3);
        ull s = add2(s01, s23);
        float2 sf = unpk(s);
        g_s[row] = sf.x + sf.y + xg;

        if (tid < 128) {
            asm volatile("bar.sync 1, 512;" ::: "memory");
            float gi = g_s[tid];
            float gf = g_s[tid + 128];
            float gg = g_s[tid + 256];
            float go = g_s[tid + 384];
            float c = fast_sig(gf) * c_reg + fast_sig(gi) * fast_tanh(gg);
            c_reg = c;
            float h = fast_sig(go) * fast_tanh(c);
            hA[tid] = h;
            asm volatile("bar.arrive 2, 512;" ::: "memory");
            leaf[(size_t)t * Hc + tid] = h;   // after arrive: off critical path
        } else {
            asm volatile("bar.arrive 1, 512;" ::: "memory");
            asm volatile("bar.sync 2, 512;" ::: "memory");
        }
        xg = xg_n;
    }

    if (tid == 0) {
        long long dt = clock64() - t_start;
        printf("LSTM cycles total=%lld per_step=%lld\n", dt, dt / Lc);
    }
}

// ---------------- Stage C: bottom-up pair fusion (8 nodes/block) ----------
__global__ void p2h_kernel(const float* __restrict__ Wp, const float* __restrict__ bp,
                           int base, int count) {
    int n0 = base + blockIdx.x * 8;
    __shared__ float pair[8][256];
    int tid = threadIdx.x;  // 128
#pragma unroll
    for (int b = 0; b < 8; b++) {
        int node = n0 + b;
        if (node < base + count) {
            pair[b][tid]       = g_hidden[(size_t)(2 * node + 1) * Hc + tid];
            pair[b][tid + 128] = g_hidden[(size_t)(2 * node + 2) * Hc + tid];
        } else {
            pair[b][tid] = 0.f; pair[b][tid + 128] = 0.f;
        }
    }
    __syncthreads();
    float a[8] = {};
    const float4* wv4 = (const float4*)(Wp + (size_t)tid * 256);
#pragma unroll 4
    for (int k = 0; k < 64; k++) {
        float4 wv = __ldg(&wv4[k]);
#pragma unroll
        for (int b = 0; b < 8; b++) {
            float4 v = ((const float4*)pair[b])[k];
            a[b] += wv.x * v.x + wv.y * v.y + wv.z * v.z + wv.w * v.w;
        }
    }
    float bias = bp[tid];
#pragma unroll
    for (int b = 0; b < 8; b++) {
        int node = n0 + b;
        if (node < base + count)
            g_hidden[(size_t)node * Hc + tid] = a[b] + bias;
    }
}

// ---------------- Stage D: unary factors (+ v2f init, f2n root zero) ------
__global__ void unary_kernel(const float* __restrict__ W_uni, const float* __restrict__ b_uni) {
    int node = blockIdx.x;
    int t = threadIdx.x;  // 64
    __shared__ float hs[128];
    hs[t] = g_hidden[(size_t)node * Hc + t];
    hs[t + 64] = g_hidden[(size_t)node * Hc + 64 + t];
    __syncthreads();
    float acc = b_uni[t];
    const float4* w = (const float4*)(W_uni + (size_t)t * 128);
    const float4* h4 = (const float4*)hs;
#pragma unroll
    for (int k = 0; k < 32; k++) {
        float4 wv = __ldg(&w[k]);
        float4 hv = h4[k];
        acc += wv.x * hv.x + wv.y * hv.y + wv.z * hv.z + wv.w * hv.w;
    }
    g_unary[(size_t)node * Tc + t] = acc;
    g_v2f[(size_t)node * Tc + t] = acc;
    if (node == 0) g_f2n[t] = 0.f;
}

// ---------------- Stage E: edge factor GEMM (f32x2) -----------------------
__global__ void __launch_bounds__(256) edge_gemm_kernel(const float* __restrict__ W,
                                                        const float* __restrict__ bias) {
    const int M = NEDGE;
    __shared__ float As[16][132];
    __shared__ float Bs[16][132];
    int m0 = blockIdx.y * 128;
    int n0 = blockIdx.x * 128;
    int tid = threadIdx.x;
    int tx = tid & 15, ty = tid >> 4;
    ull accp[8][4];
#pragma unroll
    for (int i = 0; i < 8; i++)
#pragma unroll
        for (int j = 0; j < 4; j++) accp[i][j] = 0ull;

    for (int k0 = 0; k0 < 256; k0 += 16) {
#pragma unroll
        for (int i = 0; i < 2; i++) {
            int idx = tid + i * 256;
            int m = idx & 127, k4 = idx >> 7;
            int e = m0 + m;
            float4 v = make_float4(0.f, 0.f, 0.f, 0.f);
            if (e < M) {
                int kk = k0 + k4 * 4;
                int child = e + 1, parent = e >> 1;
                const float* src = (kk < 128)
                    ? g_hidden + (size_t)parent * Hc + kk
                    : g_hidden + (size_t)child * Hc + (kk - 128);
                v = *(const float4*)src;
            }
            As[k4 * 4 + 0][m] = v.x; As[k4 * 4 + 1][m] = v.y;
            As[k4 * 4 + 2][m] = v.z; As[k4 * 4 + 3][m] = v.w;
        }
#pragma unroll
        for (int i = 0; i < 2; i++) {
            int idx = tid + i * 256;
            int n = idx & 127, k4 = idx >> 7;
            float4 v = __ldg((const float4*)(W + (size_t)(n0 + n) * 256 + k0 + k4 * 4));
            Bs[k4 * 4 + 0][n] = v.x; Bs[k4 * 4 + 1][n] = v.y;
            Bs[k4 * 4 + 2][n] = v.z; Bs[k4 * 4 + 3][n] = v.w;
        }
        __syncthreads();
#pragma unroll
        for (int kk = 0; kk < 16; kk++) {
            float4 aA = *(const float4*)&As[kk][ty * 4];
            float4 aB = *(const float4*)&As[kk][64 + ty * 4];
            ulonglong2 b0 = *(const ulonglong2*)&Bs[kk][tx * 4];
            ulonglong2 b1 = *(const ulonglong2*)&Bs[kk][64 + tx * 4];
            ull b[4] = {b0.x, b0.y, b1.x, b1.y};
            float a[8] = {aA.x, aA.y, aA.z, aA.w, aB.x, aB.y, aB.z, aB.w};
#pragma unroll
            for (int i = 0; i < 8; i++) {
                ull as = splat2(a[i]);
#pragma unroll
                for (int j = 0; j < 4; j++) fma2(accp[i][j], as, b[j]);
            }
        }
        __syncthreads();
    }
#pragma unroll
    for (int hi = 0; hi < 2; hi++) {
#pragma unroll
        for (int i = 0; i < 4; i++) {
            int m = m0 + hi * 64 + ty * 4 + i;
            if (m < M) {
#pragma unroll
                for (int hj = 0; hj < 2; hj++) {
                    int n = n0 + hj * 64 + tx * 4;
                    float2 v0 = unpk(accp[hi * 4 + i][hj * 2 + 0]);
                    float2 v1 = unpk(accp[hi * 4 + i][hj * 2 + 1]);
                    float4 o = make_float4(v0.x + bias[n], v0.y + bias[n + 1],
                                           v1.x + bias[n + 2], v1.y + bias[n + 3]);
                    *(float4*)(g_edge + (size_t)m * 4096 + n) = o;
                }
            }
        }
    }
}

// ---------------- Stage F: upward pass (one level) ------------------------
__global__ void up_kernel(int base, int leafLevel, int hasParent) {
    int idx = base + blockIdx.x;
    int t = threadIdx.x;  // 64
    __shared__ float v[64];
    float val = g_v2f[(size_t)idx * Tc + t];
    if (!leafLevel) {
        val += g_f2p[(size_t)(2 * idx + 1) * Tc + t] + g_f2p[(size_t)(2 * idx + 2) * Tc + t];
        g_v2f[(size_t)idx * Tc + t] = val;
    }
    v[t] = val;
    __syncthreads();
    if (hasParent) {
        const float4* row = (const float4*)(g_edge + (size_t)(idx - 1) * 4096 + t * 64);
        float r[64];
#pragma unroll
        for (int c = 0; c < 16; c++) {
            float4 x = __ldg(row + c);
            r[4 * c] = x.x; r[4 * c + 1] = x.y; r[4 * c + 2] = x.z; r[4 * c + 3] = x.w;
        }
        float m = -3.4e38f;
#pragma unroll
        for (int c = 0; c < 64; c++) { r[c] += v[c]; m = fmaxf(m, r[c]); }
        float s = 0.f;
#pragma unroll
        for (int c = 0; c < 64; c++) s += __expf(r[c] - m);
        g_f2p[(size_t)idx * Tc + t] = m + __logf(s);
    }
}

// ---------------- Stage G: downward pass (one level) ----------------------
__global__ void down_kernel(int base) {
    int idx = base + blockIdx.x;
    int t = threadIdx.x;  // 64
    int par = (idx - 1) >> 1;
    int sib = (idx & 1) ? idx + 1 : idx - 1;
    __shared__ float p[64];
    p[t] = g_unary[(size_t)par * Tc + t] + g_f2n[(size_t)par * Tc + t]
         + g_f2p[(size_t)sib * Tc + t];
    __syncthreads();
    const float* e0 = g_edge + (size_t)(idx - 1) * 4096 + t;
    float r[64];
    float m = -3.4e38f;
#pragma unroll
    for (int tp = 0; tp < 64; tp++) {
        r[tp] = e0[(size_t)tp * 64] + p[tp];
        m = fmaxf(m, r[tp]);
    }
    float s = 0.f;
#pragma unroll
    for (int tp = 0; tp < 64; tp++) s += __expf(r[tp] - m);
    g_f2n[(size_t)idx * Tc + t] = m + __logf(s);
}

// ---------------- Stage H: beliefs + postorder scatter --------------------
__global__ void out_kernel(float* __restrict__ out) {
    int node = blockIdx.x;
    int t = threadIdx.x;  // 64
    int x = node + 1;
    int d = 31 - __clz(x);
    int start = 0, size = Nc;
    for (int b = d - 1; b >= 0; b--) {
        int half = (size - 1) >> 1;
        if ((x >> b) & 1) start += half;
        size = half;
    }
    int post = start + size - 1;
    out[(size_t)post * Tc + t] = g_v2f[(size_t)node * Tc + t] + g_f2n[(size_t)node * Tc + t];
}

// ---------------- launch ---------------------------------------------------
extern "C" void kernel_launch(void* const* d_in, const int* in_sizes, int n_in,
                              void* d_out, int out_size) {
    const int*   tokens = (const int*)d_in[0];
    const float* emb    = (const float*)d_in[1];
    const float* W_ih   = (const float*)d_in[2];
    const float* W_hh   = (const float*)d_in[3];
    const float* b_ih   = (const float*)d_in[4];
    const float* b_hh   = (const float*)d_in[5];
    const float* W_p2h  = (const float*)d_in[6];
    const float* b_p2h  = (const float*)d_in[7];
    const float* W_uni  = (const float*)d_in[8];
    const float* b_uni  = (const float*)d_in[9];
    const float* W_edge = (const float*)d_in[10];
    const float* b_edge = (const float*)d_in[11];
    float* out = (float*)d_out;

    // A: embedding + input projection
    embed_gemm_kernel<<<Lc / 4, 128>>>(tokens, emb, W_ih, b_ih, b_hh);
    // B: sequential LSTM
    lstm_kernel<<<1, 512>>>(W_hh);
    // C: bottom-up fusion, levels D-1 .. 0
    for (int d = Dc - 1; d >= 0; d--) {
        int base = (1 << d) - 1;
        int count = 1 << d;
        p2h_kernel<<<(count + 7) / 8, 128>>>(W_p2h, b_p2h, base, count);
    }
    // D: unary factors
    unary_kernel<<<Nc, 64>>>(W_uni, b_uni);
    // E: edge factor GEMM
    {
        dim3 grid(4096 / 128, (NEDGE + 127) / 128);
        edge_gemm_kernel<<<grid, 256>>>(W_edge, b_edge);
    }
    // F: upward pass, levels D .. 0
    for (int d = Dc; d >= 0; d--) {
        int base = (1 << d) - 1;
        up_kernel<<<(1 << d), 64>>>(base, d == Dc ? 1 : 0, d > 0 ? 1 : 0);
    }
    // G: downward pass, levels 1 .. D
    for (int d = 1; d <= Dc; d++) {
        int base = (1 << d) - 1;
        down_kernel<<<(1 << d), 64>>>(base);
    }
    // H: beliefs in postorder
    out_kernel<<<Nc, 64>>>(out);
}